// round 14
// baseline (speedup 1.0000x reference)
#include <cuda_runtime.h>
#include <cuda_fp16.h>
#include <math.h>
#include <stdint.h>

#define BB 2
#define TT 2048
#define DD 1024
#define HH 16
#define HD 64
#define MROWS (BB*TT)   // 4096

// ---------------------------------------------------------------------------
// Scratch (__device__ globals per allocation-free rule)
// ---------------------------------------------------------------------------
__device__ __half g_x0[MROWS*DD], g_x1[MROWS*DD];
__device__ __half g_q0[MROWS*DD], g_q1[MROWS*DD];
__device__ __half g_k[MROWS*DD];
__device__ __half g_v[MROWS*DD];
__device__ __half g_a0[MROWS*DD], g_a1[MROWS*DD];
__device__ __half g_wq[DD*DD], g_wk[DD*DD], g_wv[DD*DD], g_wo[DD*DD];

// ---------------------------------------------------------------------------
// PTX helpers
// ---------------------------------------------------------------------------
__device__ __forceinline__ uint32_t smem_u32(const void* p) {
    uint32_t a;
    asm("{ .reg .u64 t; cvta.to.shared.u64 t, %1; cvt.u32.u64 %0, t; }"
        : "=r"(a) : "l"(p));
    return a;
}

#define CP16(dst, src) \
    asm volatile("cp.async.cg.shared.global [%0], [%1], 16;" \
        :: "r"(dst), "l"(src) : "memory")
#define CP_COMMIT() asm volatile("cp.async.commit_group;" ::: "memory")
#define CP_WAIT1()  asm volatile("cp.async.wait_group 1;" ::: "memory")
#define CP_WAIT0()  asm volatile("cp.async.wait_group 0;" ::: "memory")

#define LDSM_X4(r, a) \
    asm volatile("ldmatrix.sync.aligned.m8n8.x4.shared.b16 {%0,%1,%2,%3}, [%4];" \
        : "=r"((r)[0]), "=r"((r)[1]), "=r"((r)[2]), "=r"((r)[3]) : "r"(a))
#define LDSM_X4_T(r, a) \
    asm volatile("ldmatrix.sync.aligned.m8n8.x4.trans.shared.b16 {%0,%1,%2,%3}, [%4];" \
        : "=r"((r)[0]), "=r"((r)[1]), "=r"((r)[2]), "=r"((r)[3]) : "r"(a))

#define MMA_F16(c, a, b0, b1) \
    asm volatile("mma.sync.aligned.m16n8k16.row.col.f32.f16.f16.f32 " \
        "{%0,%1,%2,%3}, {%4,%5,%6,%7}, {%8,%9}, {%0,%1,%2,%3};" \
        : "+f"((c)[0]), "+f"((c)[1]), "+f"((c)[2]), "+f"((c)[3]) \
        : "r"((a)[0]), "r"((a)[1]), "r"((a)[2]), "r"((a)[3]), \
          "r"(b0), "r"(b1))

__device__ __forceinline__ void split2h(float x, float y,
                                        uint32_t& hi, uint32_t& lo) {
    __half hx = __float2half_rn(x);
    __half hy = __float2half_rn(y);
    __half2 h2(hx, hy);
    __half2 l2(__float2half_rn(x - __half2float(hx)),
               __float2half_rn(y - __half2float(hy)));
    hi = *(uint32_t*)&h2;
    lo = *(uint32_t*)&l2;
}
__device__ __forceinline__ uint32_t pack2h(float x, float y) {
    __half2 h2(__float2half_rn(x), __float2half_rn(y));
    return *(uint32_t*)&h2;
}

// ---------------------------------------------------------------------------
// Prep kernels
// ---------------------------------------------------------------------------
__global__ void fsplit_kernel(const float* __restrict__ X,
                              __half* __restrict__ H,
                              __half* __restrict__ L)
{
    const int i = (blockIdx.x * blockDim.x + threadIdx.x) * 4;
    float4 xv = *(const float4*)(X + i);
    uint32_t h0, l0, h1, l1;
    split2h(xv.x, xv.y, h0, l0);
    split2h(xv.z, xv.w, h1, l1);
    *(uint32_t*)(H + i)     = h0;  *(uint32_t*)(H + i + 2) = h1;
    *(uint32_t*)(L + i)     = l0;  *(uint32_t*)(L + i + 2) = l1;
}

struct TSplitArgs {
    const float* w[4];
    __half* th[4];
};

__global__ void tsplit_kernel(TSplitArgs args)
{
    __shared__ float t[32][33];
    const float* W = args.w[blockIdx.z];
    __half* Th = args.th[blockIdx.z];
    const int n0 = blockIdx.x * 32, k0 = blockIdx.y * 32;
    const int tx = threadIdx.x, ty = threadIdx.y;
    #pragma unroll
    for (int i = 0; i < 32; i += 8)
        t[ty + i][tx] = W[(size_t)(k0 + ty + i) * DD + n0 + tx];
    __syncthreads();
    #pragma unroll
    for (int i = 0; i < 32; i += 8) {
        Th[(size_t)(n0 + ty + i) * DD + k0 + tx] =
            __float2half_rn(t[tx][ty + i]);
    }
}

// ---------------------------------------------------------------------------
// fp16 HMMA GEMM: 512 threads (16 warps, 4x4 grid, warp tile 32x32),
// 2-term A-split, GBK=32, 3-stage cp.async, 1 sync/iter.
// ---------------------------------------------------------------------------
#define GM 128
#define GN 128
#define GBK 32
#define NKT (DD / GBK)       // 32
#define SSTRB 80
#define OMAT (128 * SSTRB)   // 10240
#define OA1 (OMAT)
#define OB  (2*OMAT)
#define SSZ (3*OMAT)         // 30720 per stage
#define GEMM_SMEM (3*SSZ)    // 92160
#define GTHREADS 512

struct QKVArgs {
    const __half* w[3];
    const float* bias[3];
    __half *ch[3], *cl[3];
};

// Per-thread loader state: 3 chunks of 16B per stage.
struct GLoad {
    const __half* src[3];
    uint32_t dst[3];
};

__device__ __forceinline__ GLoad gemm_loader_init(
    int tid, const __half* A0, const __half* A1, const __half* B,
    int m0, int n0)
{
    GLoad g;
    #pragma unroll
    for (int j = 0; j < 3; j++) {
        const int cidx = tid + j * GTHREADS;     // 0..1535
        const int mat = cidx >> 9;               // 0..2
        const int within = cidx & 511;
        const int r  = within >> 2;              // 0..127
        const int cb = (within & 3) * 16;        // byte col 0..48
        const uint32_t moff = (mat == 0) ? 0u : (mat == 1) ? (uint32_t)OA1
                                                           : (uint32_t)OB;
        const __half* base = (mat == 0) ? A0 + (size_t)(m0 + r) * DD
                           : (mat == 1) ? A1 + (size_t)(m0 + r) * DD
                                        : B  + (size_t)(n0 + r) * DD;
        g.src[j] = base + cb / 2;
        g.dst[j] = moff + (uint32_t)r * SSTRB + cb;
    }
    return g;
}

__device__ __forceinline__ void gemm_stage_load(
    uint32_t sbase, const GLoad& g, int ko)
{
    #pragma unroll
    for (int j = 0; j < 3; j++)
        CP16(sbase + g.dst[j], g.src[j] + ko);
    CP_COMMIT();
}

__device__ __forceinline__ void gemm_core(
    uint32_t sb, int tid,
    const __half* A0, const __half* A1, const __half* B,
    int m0, int n0, float c[2][4][4])
{
    const int wid  = tid >> 5;
    const int lane = tid & 31;
    const int wm   = wid >> 2;   // 0..3
    const int wn   = wid & 3;    // 0..3

    GLoad g = gemm_loader_init(tid, A0, A1, B, m0, n0);

    const uint32_t a_base = sb + (uint32_t)(wm * 32 + (lane & 15)) * SSTRB
                          + (uint32_t)(lane >> 4) * 16;
    const uint32_t b_base = sb + OB + (uint32_t)(wn * 32 + (lane & 15)) * SSTRB
                          + (uint32_t)(lane >> 4) * 16;

    #pragma unroll
    for (int mt = 0; mt < 2; mt++)
        #pragma unroll
        for (int nt = 0; nt < 4; nt++)
            #pragma unroll
            for (int i = 0; i < 4; i++) c[mt][nt][i] = 0.f;

    gemm_stage_load(sb,       g, 0);
    gemm_stage_load(sb + SSZ, g, GBK);

    uint32_t cur = 0;
    for (int kt = 0; kt < NKT; kt++) {
        if (kt + 1 < NKT) CP_WAIT1(); else CP_WAIT0();
        __syncthreads();

        if (kt + 2 < NKT) {
            uint32_t pre = cur + 2 * SSZ;
            if (pre >= 3 * SSZ) pre -= 3 * SSZ;
            gemm_stage_load(sb + pre, g, (kt + 2) * GBK);
        }

        #pragma unroll
        for (int ks = 0; ks < 2; ks++) {
            const uint32_t ksb = cur + ks * 32;
            uint32_t ah[2][4], al[2][4], bb[2][4];
            #pragma unroll
            for (int mt = 0; mt < 2; mt++) {
                const uint32_t aa = a_base + ksb + (uint32_t)(mt * 16) * SSTRB;
                LDSM_X4(ah[mt], aa);
                LDSM_X4(al[mt], aa + OA1);
            }
            #pragma unroll
            for (int ntp = 0; ntp < 2; ntp++) {
                const uint32_t ba = b_base + ksb + (uint32_t)(ntp * 16) * SSTRB;
                LDSM_X4(bb[ntp], ba);
            }
            #pragma unroll
            for (int mt = 0; mt < 2; mt++)
                #pragma unroll
                for (int ntp = 0; ntp < 2; ntp++) {
                    MMA_F16(c[mt][2*ntp],   ah[mt], bb[ntp][0], bb[ntp][2]);
                    MMA_F16(c[mt][2*ntp],   al[mt], bb[ntp][0], bb[ntp][2]);
                    MMA_F16(c[mt][2*ntp+1], ah[mt], bb[ntp][1], bb[ntp][3]);
                    MMA_F16(c[mt][2*ntp+1], al[mt], bb[ntp][1], bb[ntp][3]);
                }
        }

        cur += SSZ;
        if (cur == 3 * SSZ) cur = 0;
    }
}

// Fused QKV GEMM: widx 0 (Q) writes hi/lo split; widx 1,2 (K,V) single fp16.
__global__ __launch_bounds__(GTHREADS, 1) void gemm_qkv_kernel(
    const __half* __restrict__ A0, const __half* __restrict__ A1,
    QKVArgs args)
{
    extern __shared__ char smem[];
    const uint32_t sb = smem_u32(smem);
    const int tid  = threadIdx.x;
    const int widx = blockIdx.x >> 3;
    const int n0   = (blockIdx.x & 7) * GN;
    const int m0   = blockIdx.y * GM;

    float c[2][4][4];
    gemm_core(sb, tid, A0, A1, args.w[widx], m0, n0, c);

    const float* bias = args.bias[widx];
    __half* Ch = args.ch[widx];
    __half* Cl = args.cl[widx];
    const int wid  = tid >> 5;
    const int lane = tid & 31;
    const int wm = wid >> 2, wn = wid & 3;
    const int lr = lane >> 2, lc = lane & 3;
    #pragma unroll
    for (int mt = 0; mt < 2; mt++) {
        const int row = m0 + wm * 32 + mt * 16 + lr;
        #pragma unroll
        for (int nt = 0; nt < 4; nt++) {
            const int col = n0 + wn * 32 + nt * 8 + 2 * lc;
            const float b0 = bias[col], b1 = bias[col + 1];
            const float o00 = c[mt][nt][0] + b0, o01 = c[mt][nt][1] + b1;
            const float o10 = c[mt][nt][2] + b0, o11 = c[mt][nt][3] + b1;
            if (widx == 0) {
                uint32_t h, l;
                split2h(o00, o01, h, l);
                *(uint32_t*)(Ch + (size_t)row * DD + col) = h;
                *(uint32_t*)(Cl + (size_t)row * DD + col) = l;
                split2h(o10, o11, h, l);
                *(uint32_t*)(Ch + (size_t)(row + 8) * DD + col) = h;
                *(uint32_t*)(Cl + (size_t)(row + 8) * DD + col) = l;
            } else {
                *(uint32_t*)(Ch + (size_t)row * DD + col)       = pack2h(o00, o01);
                *(uint32_t*)(Ch + (size_t)(row + 8) * DD + col) = pack2h(o10, o11);
            }
        }
    }
}

// Wo GEMM: fp32 output
__global__ __launch_bounds__(GTHREADS, 1) void gemm_o_kernel(
    const __half* __restrict__ A0, const __half* __restrict__ A1,
    const __half* __restrict__ B,
    const float* __restrict__ bias, float* __restrict__ C)
{
    extern __shared__ char smem[];
    const uint32_t sb = smem_u32(smem);
    const int tid = threadIdx.x;
    const int n0  = blockIdx.x * GN;
    const int m0  = blockIdx.y * GM;

    float c[2][4][4];
    gemm_core(sb, tid, A0, A1, B, m0, n0, c);

    const int wid  = tid >> 5;
    const int lane = tid & 31;
    const int wm = wid >> 2, wn = wid & 3;
    const int lr = lane >> 2, lc = lane & 3;
    #pragma unroll
    for (int mt = 0; mt < 2; mt++) {
        const int row = m0 + wm * 32 + mt * 16 + lr;
        #pragma unroll
        for (int nt = 0; nt < 4; nt++) {
            const int col = n0 + wn * 32 + nt * 8 + 2 * lc;
            const float b0 = bias[col], b1 = bias[col + 1];
            *(float2*)(C + (size_t)row * DD + col) =
                make_float2(c[mt][nt][0] + b0, c[mt][nt][1] + b1);
            *(float2*)(C + (size_t)(row + 8) * DD + col) =
                make_float2(c[mt][nt][2] + b0, c[mt][nt][3] + b1);
        }
    }
}

// ---------------------------------------------------------------------------
// fp16 flash attention: Br=128, Bc=64, Q split / K,V single,
// 3-stage KV pipeline, 1 sync/iter.  (round-11/13 config)
// ---------------------------------------------------------------------------
#define FRS 144
#define FOQ1 (128*FRS)
#define FOKV (2*128*FRS)          // 36864
#define FOV  (64*FRS)
#define FSTG (2*64*FRS)           // 18432 per stage
#define FATTN_SMEM (FOKV + 3*FSTG)   // 92160

__device__ __forceinline__ void load_kv_tile(
    uint32_t sb, uint32_t stgoff,
    const __half* Kg, const __half* Vg,
    size_t gbase, int tid)
{
    const uint32_t base = sb + FOKV + stgoff;
    #pragma unroll
    for (int it = 0; it < 4; it++) {
        const int i2 = ((it & 1) << 8) + tid;
        const int r  = i2 >> 3;
        const int cb = (i2 & 7) * 16;
        const __half* sp = (it >> 1) ? Vg : Kg;
        const uint32_t off = (it >> 1) ? FOV : 0;
        CP16(base + off + (uint32_t)r * FRS + cb,
             sp + gbase + (size_t)r * DD + cb / 2);
    }
    CP_COMMIT();
}

__global__ __launch_bounds__(256, 1) void fattn_kernel(
    const __half* __restrict__ Q0g, const __half* __restrict__ Q1g,
    const __half* __restrict__ Kg,  const __half* __restrict__ Vg,
    __half* __restrict__ A0out, __half* __restrict__ A1out)
{
    extern __shared__ char smem[];
    const uint32_t sb = smem_u32(smem);
    const int tid  = threadIdx.x;
    const int wid  = tid >> 5;
    const int lane = tid & 31;
    const int gid  = lane >> 2;
    const int t4   = lane & 3;

    const int qtile = (gridDim.x - 1) - blockIdx.x;
    const int q0 = qtile * 128;
    const int b  = blockIdx.y >> 4;
    const int h  = blockIdx.y & 15;
    const size_t hb = (size_t)(b * TT) * DD + h * HD;

    #pragma unroll
    for (int it = 0; it < 8; it++) {
        const int i2 = ((it & 3) << 8) + tid;
        const int r  = i2 >> 3;
        const int cb = (i2 & 7) * 16;
        const __half* sp = (it >> 2) ? Q1g : Q0g;
        const uint32_t off = (it >> 2) ? FOQ1 : 0;
        CP16(sb + off + (uint32_t)r * FRS + cb,
             sp + hb + (size_t)(q0 + r) * DD + cb / 2);
    }
    CP_COMMIT();

    const int ntiles = q0 / 64 + 2;
    load_kv_tile(sb, 0,    Kg, Vg, hb, tid);
    load_kv_tile(sb, FSTG, Kg, Vg, hb + (size_t)64 * DD, tid);

    const uint32_t qa0 = sb + (uint32_t)(wid * 16 + (lane & 15)) * FRS
                       + (uint32_t)(lane >> 4) * 16;
    const uint32_t qa1 = qa0 + FOQ1;
    const uint32_t kb4 = sb + FOKV + (uint32_t)(lane & 15) * FRS
                       + (uint32_t)(lane >> 4) * 16;
    const uint32_t vb4 = sb + FOKV + FOV + (uint32_t)(lane & 15) * FRS
                       + (uint32_t)(lane >> 4) * 16;

    float oc[8][4];
    #pragma unroll
    for (int nt = 0; nt < 8; nt++)
        #pragma unroll
        for (int e = 0; e < 4; e++) oc[nt][e] = 0.f;
    float m0v = -1e30f, m1v = -1e30f, l0 = 0.f, l1 = 0.f;

    const int r0 = q0 + wid * 16 + gid;
    const int r1 = r0 + 8;

    uint32_t cur = 0;
    for (int kt = 0; kt < ntiles; kt++) {
        const int kv0 = kt * 64;
        if (kt + 1 < ntiles) CP_WAIT1(); else CP_WAIT0();
        __syncthreads();

        if (kt + 2 < ntiles) {
            uint32_t pre = cur + 2 * FSTG;
            if (pre >= 3 * FSTG) pre -= 3 * FSTG;
            load_kv_tile(sb, pre, Kg, Vg, hb + (size_t)(kv0 + 128) * DD, tid);
        }

        float sc[8][4];
        #pragma unroll
        for (int nt = 0; nt < 8; nt++)
            #pragma unroll
            for (int e = 0; e < 4; e++) sc[nt][e] = 0.f;

        #pragma unroll
        for (int ks = 0; ks < 4; ks++) {
            uint32_t ah[4], al[4];
            LDSM_X4(ah, qa0 + ks * 32);
            LDSM_X4(al, qa1 + ks * 32);
            #pragma unroll
            for (int ntp = 0; ntp < 4; ntp++) {
                uint32_t bk[4];
                const uint32_t ka = kb4 + cur + (uint32_t)(ntp * 16) * FRS + ks * 32;
                LDSM_X4(bk, ka);
                MMA_F16(sc[2*ntp],   ah, bk[0], bk[2]);
                MMA_F16(sc[2*ntp],   al, bk[0], bk[2]);
                MMA_F16(sc[2*ntp+1], ah, bk[1], bk[3]);
                MMA_F16(sc[2*ntp+1], al, bk[1], bk[3]);
            }
        }

        const bool maskt = (kt >= ntiles - 2);
        #pragma unroll
        for (int nt = 0; nt < 8; nt++) {
            #pragma unroll
            for (int e = 0; e < 4; e++) {
                float s = sc[nt][e] * 0.125f;
                if (maskt) {
                    const int col = kv0 + nt * 8 + 2 * t4 + (e & 1);
                    const int row = (e < 2) ? r0 : r1;
                    if (col > row) s = -1e30f;
                }
                sc[nt][e] = s;
            }
        }

        float mx0 = -1e30f, mx1 = -1e30f;
        #pragma unroll
        for (int nt = 0; nt < 8; nt++) {
            mx0 = fmaxf(mx0, fmaxf(sc[nt][0], sc[nt][1]));
            mx1 = fmaxf(mx1, fmaxf(sc[nt][2], sc[nt][3]));
        }
        mx0 = fmaxf(mx0, __shfl_xor_sync(0xffffffffu, mx0, 1));
        mx0 = fmaxf(mx0, __shfl_xor_sync(0xffffffffu, mx0, 2));
        mx1 = fmaxf(mx1, __shfl_xor_sync(0xffffffffu, mx1, 1));
        mx1 = fmaxf(mx1, __shfl_xor_sync(0xffffffffu, mx1, 2));

        const float mn0 = fmaxf(m0v, mx0);
        const float mn1 = fmaxf(m1v, mx1);
        const float al0 = __expf(m0v - mn0);
        const float al1 = __expf(m1v - mn1);

        float s0 = 0.f, s1 = 0.f;
        #pragma unroll
        for (int nt = 0; nt < 8; nt++) {
            sc[nt][0] = __expf(sc[nt][0] - mn0);
            sc[nt][1] = __expf(sc[nt][1] - mn0);
            sc[nt][2] = __expf(sc[nt][2] - mn1);
            sc[nt][3] = __expf(sc[nt][3] - mn1);
            s0 += sc[nt][0] + sc[nt][1];
            s1 += sc[nt][2] + sc[nt][3];
        }
        s0 += __shfl_xor_sync(0xffffffffu, s0, 1);
        s0 += __shfl_xor_sync(0xffffffffu, s0, 2);
        s1 += __shfl_xor_sync(0xffffffffu, s1, 1);
        s1 += __shfl_xor_sync(0xffffffffu, s1, 2);
        l0 = l0 * al0 + s0;
        l1 = l1 * al1 + s1;
        #pragma unroll
        for (int nt = 0; nt < 8; nt++) {
            oc[nt][0] *= al0;
            oc[nt][1] *= al0;
            oc[nt][2] *= al1;
            oc[nt][3] *= al1;
        }
        m0v = mn0;
        m1v = mn1;

        #pragma unroll
        for (int t = 0; t < 4; t++) {
            uint32_t ph[4], pl[4];
            split2h(sc[2*t][0],   sc[2*t][1],   ph[0], pl[0]);
            split2h(sc[2*t][2],   sc[2*t][3],   ph[1], pl[1]);
            split2h(sc[2*t+1][0], sc[2*t+1][1], ph[2], pl[2]);
            split2h(sc[2*t+1][2], sc[2*t+1][3], ph[3], pl[3]);
            #pragma unroll
            for (int ntp = 0; ntp < 4; ntp++) {
                uint32_t vh[4];
                const uint32_t va = vb4 + cur + (uint32_t)(t * 16) * FRS + ntp * 32;
                LDSM_X4_T(vh, va);
                MMA_F16(oc[2*ntp],   ph, vh[0], vh[1]);
                MMA_F16(oc[2*ntp],   pl, vh[0], vh[1]);
                MMA_F16(oc[2*ntp+1], ph, vh[2], vh[3]);
                MMA_F16(oc[2*ntp+1], pl, vh[2], vh[3]);
            }
        }

        cur += FSTG;
        if (cur == 3 * FSTG) cur = 0;
    }

    const float inv0 = 1.f / l0;
    const float inv1 = 1.f / l1;
    #pragma unroll
    for (int nt = 0; nt < 8; nt++) {
        const int col = nt * 8 + 2 * t4;
        uint32_t hh, ll;
        split2h(oc[nt][0] * inv0, oc[nt][1] * inv0, hh, ll);
        *(uint32_t*)(A0out + hb + (size_t)r0 * DD + col) = hh;
        *(uint32_t*)(A1out + hb + (size_t)r0 * DD + col) = ll;
        split2h(oc[nt][2] * inv1, oc[nt][3] * inv1, hh, ll);
        *(uint32_t*)(A0out + hb + (size_t)r1 * DD + col) = hh;
        *(uint32_t*)(A1out + hb + (size_t)r1 * DD + col) = ll;
    }
}

// ---------------------------------------------------------------------------
extern "C" void kernel_launch(void* const* d_in, const int* in_sizes, int n_in,
                              void* d_out, int out_size)
{
    (void)in_sizes; (void)n_in; (void)out_size;
    const float* x  = (const float*)d_in[0];
    const float* Wq = (const float*)d_in[2];
    const float* bq = (const float*)d_in[3];
    const float* Wk = (const float*)d_in[4];
    const float* bk = (const float*)d_in[5];
    const float* Wv = (const float*)d_in[6];
    const float* bv = (const float*)d_in[7];
    const float* Wo = (const float*)d_in[8];
    const float* bo = (const float*)d_in[9];
    float* out = (float*)d_out;

    __half *x0, *x1, *q0, *q1, *k, *v, *a0, *a1;
    cudaGetSymbolAddress((void**)&x0, g_x0);
    cudaGetSymbolAddress((void**)&x1, g_x1);
    cudaGetSymbolAddress((void**)&q0, g_q0);
    cudaGetSymbolAddress((void**)&q1, g_q1);
    cudaGetSymbolAddress((void**)&k,  g_k);
    cudaGetSymbolAddress((void**)&v,  g_v);
    cudaGetSymbolAddress((void**)&a0, g_a0);
    cudaGetSymbolAddress((void**)&a1, g_a1);
    __half *wq, *wk, *wv, *wo;
    cudaGetSymbolAddress((void**)&wq, g_wq);
    cudaGetSymbolAddress((void**)&wk, g_wk);
    cudaGetSymbolAddress((void**)&wv, g_wv);
    cudaGetSymbolAddress((void**)&wo, g_wo);

    cudaFuncSetAttribute(gemm_qkv_kernel,
                         cudaFuncAttributeMaxDynamicSharedMemorySize, GEMM_SMEM);
    cudaFuncSetAttribute(gemm_o_kernel,
                         cudaFuncAttributeMaxDynamicSharedMemorySize, GEMM_SMEM);
    cudaFuncSetAttribute(fattn_kernel,
                         cudaFuncAttributeMaxDynamicSharedMemorySize, FATTN_SMEM);

    const int nElem = MROWS * DD;
    fsplit_kernel<<<nElem / 4 / 256, 256>>>(x, x0, x1);

    TSplitArgs ts;
    ts.w[0] = Wq;  ts.w[1] = Wk;  ts.w[2] = Wv;  ts.w[3] = Wo;
    ts.th[0] = wq; ts.th[1] = wk; ts.th[2] = wv; ts.th[3] = wo;
    tsplit_kernel<<<dim3(DD / 32, DD / 32, 4), dim3(32, 8)>>>(ts);

    QKVArgs args;
    args.w[0] = wq; args.w[1] = wk; args.w[2] = wv;
    args.bias[0] = bq; args.bias[1] = bk; args.bias[2] = bv;
    args.ch[0] = q0; args.ch[1] = k; args.ch[2] = v;
    args.cl[0] = q1; args.cl[1] = nullptr; args.cl[2] = nullptr;

    gemm_qkv_kernel<<<dim3(24, MROWS / GM), GTHREADS, GEMM_SMEM>>>(x0, x1, args);

    fattn_kernel<<<dim3(TT / 128, BB * HH), 256, FATTN_SMEM>>>(
        q0, q1, k, v, a0, a1);

    gemm_o_kernel<<<dim3(DD / GN, MROWS / GM), GTHREADS, GEMM_SMEM>>>(
        a0, a1, wo, bo, out);
}

// round 15
// speedup vs baseline: 1.3424x; 1.3424x over previous
#include <cuda_runtime.h>
#include <cuda_fp16.h>
#include <math.h>
#include <stdint.h>

#define BB 2
#define TT 2048
#define DD 1024
#define HH 16
#define HD 64
#define MROWS (BB*TT)   // 4096

// ---------------------------------------------------------------------------
// Scratch (__device__ globals per allocation-free rule)
// ---------------------------------------------------------------------------
__device__ __half g_x[MROWS*DD];                    // x single fp16
__device__ __half g_q0[MROWS*DD], g_q1[MROWS*DD];   // q split hi/lo
__device__ __half g_k[MROWS*DD];
__device__ __half g_v[MROWS*DD];
__device__ __half g_a0[MROWS*DD], g_a1[MROWS*DD];   // attn out split
__device__ __half g_wq[DD*DD], g_wk[DD*DD], g_wv[DD*DD], g_wo[DD*DD];

// ---------------------------------------------------------------------------
// PTX helpers
// ---------------------------------------------------------------------------
__device__ __forceinline__ uint32_t smem_u32(const void* p) {
    uint32_t a;
    asm("{ .reg .u64 t; cvta.to.shared.u64 t, %1; cvt.u32.u64 %0, t; }"
        : "=r"(a) : "l"(p));
    return a;
}

#define CP16(dst, src) \
    asm volatile("cp.async.cg.shared.global [%0], [%1], 16;" \
        :: "r"(dst), "l"(src) : "memory")
#define CP_COMMIT() asm volatile("cp.async.commit_group;" ::: "memory")
#define CP_WAIT1()  asm volatile("cp.async.wait_group 1;" ::: "memory")
#define CP_WAIT0()  asm volatile("cp.async.wait_group 0;" ::: "memory")

#define LDSM_X4(r, a) \
    asm volatile("ldmatrix.sync.aligned.m8n8.x4.shared.b16 {%0,%1,%2,%3}, [%4];" \
        : "=r"((r)[0]), "=r"((r)[1]), "=r"((r)[2]), "=r"((r)[3]) : "r"(a))
#define LDSM_X4_T(r, a) \
    asm volatile("ldmatrix.sync.aligned.m8n8.x4.trans.shared.b16 {%0,%1,%2,%3}, [%4];" \
        : "=r"((r)[0]), "=r"((r)[1]), "=r"((r)[2]), "=r"((r)[3]) : "r"(a))

#define MMA_F16(c, a, b0, b1) \
    asm volatile("mma.sync.aligned.m16n8k16.row.col.f32.f16.f16.f32 " \
        "{%0,%1,%2,%3}, {%4,%5,%6,%7}, {%8,%9}, {%0,%1,%2,%3};" \
        : "+f"((c)[0]), "+f"((c)[1]), "+f"((c)[2]), "+f"((c)[3]) \
        : "r"((a)[0]), "r"((a)[1]), "r"((a)[2]), "r"((a)[3]), \
          "r"(b0), "r"(b1))

__device__ __forceinline__ void split2h(float x, float y,
                                        uint32_t& hi, uint32_t& lo) {
    __half hx = __float2half_rn(x);
    __half hy = __float2half_rn(y);
    __half2 h2(hx, hy);
    __half2 l2(__float2half_rn(x - __half2float(hx)),
               __float2half_rn(y - __half2float(hy)));
    hi = *(uint32_t*)&h2;
    lo = *(uint32_t*)&l2;
}
__device__ __forceinline__ uint32_t pack2h(float x, float y) {
    __half2 h2(__float2half_rn(x), __float2half_rn(y));
    return *(uint32_t*)&h2;
}

// ---------------------------------------------------------------------------
// Prep kernels
// ---------------------------------------------------------------------------
__global__ void fhalf_kernel(const float* __restrict__ X,
                             __half* __restrict__ H)
{
    const int i = (blockIdx.x * blockDim.x + threadIdx.x) * 4;
    float4 xv = *(const float4*)(X + i);
    *(uint32_t*)(H + i)     = pack2h(xv.x, xv.y);
    *(uint32_t*)(H + i + 2) = pack2h(xv.z, xv.w);
}

struct TSplitArgs {
    const float* w[4];
    __half* th[4];
};

__global__ void tsplit_kernel(TSplitArgs args)
{
    __shared__ float t[32][33];
    const float* W = args.w[blockIdx.z];
    __half* Th = args.th[blockIdx.z];
    const int n0 = blockIdx.x * 32, k0 = blockIdx.y * 32;
    const int tx = threadIdx.x, ty = threadIdx.y;
    #pragma unroll
    for (int i = 0; i < 32; i += 8)
        t[ty + i][tx] = W[(size_t)(k0 + ty + i) * DD + n0 + tx];
    __syncthreads();
    #pragma unroll
    for (int i = 0; i < 32; i += 8) {
        Th[(size_t)(n0 + ty + i) * DD + k0 + tx] =
            __float2half_rn(t[tx][ty + i]);
    }
}

// ---------------------------------------------------------------------------
// fp16 HMMA GEMM core, templated on A-split.
// 256 threads, GBK=32, 3-stage cp.async, 1 sync/iter.
// ---------------------------------------------------------------------------
#define GM 128
#define GN 128
#define GBK 32
#define NKT (DD / GBK)       // 32
#define SSTRB 80
#define OMAT (128 * SSTRB)   // 10240
#define QKV_SMEM (3 * 2 * OMAT)   // 61440 (2 mats/stage)
#define WO_SMEM  (3 * 3 * OMAT)   // 92160 (3 mats/stage)

struct QKVArgs {
    const __half* w[3];
    const float* bias[3];
    __half *ch[3], *cl[3];
};

template<bool SPLITA>
__device__ __forceinline__ void gemm_core(
    uint32_t sb, int tid,
    const __half* A0, const __half* A1, const __half* B,
    int m0, int n0, float c[4][4][4])
{
    constexpr uint32_t OBv  = (SPLITA ? 2u : 1u) * OMAT;
    constexpr uint32_t SSZv = (SPLITA ? 3u : 2u) * OMAT;

    const int wid  = tid >> 5;
    const int lane = tid & 31;
    const int wm   = wid >> 2;
    const int wn   = wid & 3;

    const int lrow = tid >> 1;
    const int lce  = (tid & 1) * 16;
    const uint32_t dstoff = lrow * SSTRB + lce * 2;
    const __half* gA0 = A0 + (size_t)(m0 + lrow) * DD + lce;
    const __half* gA1 = SPLITA ? A1 + (size_t)(m0 + lrow) * DD + lce : nullptr;
    const __half* gB  = B  + (size_t)(n0 + lrow) * DD + lce;

    const uint32_t a_base = sb + (uint32_t)(wm * 64 + (lane & 15)) * SSTRB
                          + (uint32_t)(lane >> 4) * 16;
    const uint32_t b_base = sb + OBv + (uint32_t)(wn * 32 + (lane & 15)) * SSTRB
                          + (uint32_t)(lane >> 4) * 16;

    #pragma unroll
    for (int mt = 0; mt < 4; mt++)
        #pragma unroll
        for (int nt = 0; nt < 4; nt++)
            #pragma unroll
            for (int i = 0; i < 4; i++) c[mt][nt][i] = 0.f;

    auto stage_load = [&](uint32_t s, int ko) {
        CP16(s,        gA0 + ko);  CP16(s + 16,        gA0 + ko + 8);
        if (SPLITA) {
            CP16(s + OMAT, gA1 + ko);  CP16(s + OMAT + 16, gA1 + ko + 8);
        }
        CP16(s + OBv,  gB + ko);   CP16(s + OBv + 16,  gB + ko + 8);
        CP_COMMIT();
    };

    stage_load(sb + dstoff,        0);
    stage_load(sb + SSZv + dstoff, GBK);

    uint32_t cur = 0;
    for (int kt = 0; kt < NKT; kt++) {
        if (kt + 1 < NKT) CP_WAIT1(); else CP_WAIT0();
        __syncthreads();

        if (kt + 2 < NKT) {
            uint32_t pre = cur + 2 * SSZv;
            if (pre >= 3 * SSZv) pre -= 3 * SSZv;
            stage_load(sb + pre + dstoff, (kt + 2) * GBK);
        }

        #pragma unroll
        for (int ks = 0; ks < 2; ks++) {
            const uint32_t ksb = cur + ks * 32;
            uint32_t ah[4][4], al[4][4], bb[2][4];
            #pragma unroll
            for (int mt = 0; mt < 4; mt++) {
                const uint32_t aa = a_base + ksb + (uint32_t)(mt * 16) * SSTRB;
                LDSM_X4(ah[mt], aa);
                if (SPLITA) LDSM_X4(al[mt], aa + OMAT);
            }
            #pragma unroll
            for (int ntp = 0; ntp < 2; ntp++) {
                const uint32_t ba = b_base + ksb + (uint32_t)(ntp * 16) * SSTRB;
                LDSM_X4(bb[ntp], ba);
            }
            #pragma unroll
            for (int mt = 0; mt < 4; mt++)
                #pragma unroll
                for (int ntp = 0; ntp < 2; ntp++) {
                    MMA_F16(c[mt][2*ntp],   ah[mt], bb[ntp][0], bb[ntp][2]);
                    MMA_F16(c[mt][2*ntp+1], ah[mt], bb[ntp][1], bb[ntp][3]);
                    if (SPLITA) {
                        MMA_F16(c[mt][2*ntp],   al[mt], bb[ntp][0], bb[ntp][2]);
                        MMA_F16(c[mt][2*ntp+1], al[mt], bb[ntp][1], bb[ntp][3]);
                    }
                }
        }

        cur += SSZv;
        if (cur == 3 * SSZv) cur = 0;
    }
}

// Fused QKV GEMM (A single): widx 0 (Q) writes hi/lo; widx 1,2 single fp16.
__global__ __launch_bounds__(256, 1) void gemm_qkv_kernel(
    const __half* __restrict__ A, QKVArgs args)
{
    extern __shared__ char smem[];
    const uint32_t sb = smem_u32(smem);
    const int tid  = threadIdx.x;
    const int widx = blockIdx.x >> 3;
    const int n0   = (blockIdx.x & 7) * GN;
    const int m0   = blockIdx.y * GM;

    float c[4][4][4];
    gemm_core<false>(sb, tid, A, nullptr, args.w[widx], m0, n0, c);

    const float* bias = args.bias[widx];
    __half* Ch = args.ch[widx];
    __half* Cl = args.cl[widx];
    const int wid  = tid >> 5;
    const int lane = tid & 31;
    const int wm = wid >> 2, wn = wid & 3;
    const int lr = lane >> 2, lc = lane & 3;
    #pragma unroll
    for (int mt = 0; mt < 4; mt++) {
        const int row = m0 + wm * 64 + mt * 16 + lr;
        #pragma unroll
        for (int nt = 0; nt < 4; nt++) {
            const int col = n0 + wn * 32 + nt * 8 + 2 * lc;
            const float b0 = bias[col], b1 = bias[col + 1];
            const float o00 = c[mt][nt][0] + b0, o01 = c[mt][nt][1] + b1;
            const float o10 = c[mt][nt][2] + b0, o11 = c[mt][nt][3] + b1;
            if (widx == 0) {
                uint32_t h, l;
                split2h(o00, o01, h, l);
                *(uint32_t*)(Ch + (size_t)row * DD + col) = h;
                *(uint32_t*)(Cl + (size_t)row * DD + col) = l;
                split2h(o10, o11, h, l);
                *(uint32_t*)(Ch + (size_t)(row + 8) * DD + col) = h;
                *(uint32_t*)(Cl + (size_t)(row + 8) * DD + col) = l;
            } else {
                *(uint32_t*)(Ch + (size_t)row * DD + col)       = pack2h(o00, o01);
                *(uint32_t*)(Ch + (size_t)(row + 8) * DD + col) = pack2h(o10, o11);
            }
        }
    }
}

// Wo GEMM (A split): fp32 output
__global__ __launch_bounds__(256, 1) void gemm_o_kernel(
    const __half* __restrict__ A0, const __half* __restrict__ A1,
    const __half* __restrict__ B,
    const float* __restrict__ bias, float* __restrict__ C)
{
    extern __shared__ char smem[];
    const uint32_t sb = smem_u32(smem);
    const int tid = threadIdx.x;
    const int n0  = blockIdx.x * GN;
    const int m0  = blockIdx.y * GM;

    float c[4][4][4];
    gemm_core<true>(sb, tid, A0, A1, B, m0, n0, c);

    const int wid  = tid >> 5;
    const int lane = tid & 31;
    const int wm = wid >> 2, wn = wid & 3;
    const int lr = lane >> 2, lc = lane & 3;
    #pragma unroll
    for (int mt = 0; mt < 4; mt++) {
        const int row = m0 + wm * 64 + mt * 16 + lr;
        #pragma unroll
        for (int nt = 0; nt < 4; nt++) {
            const int col = n0 + wn * 32 + nt * 8 + 2 * lc;
            const float b0 = bias[col], b1 = bias[col + 1];
            *(float2*)(C + (size_t)row * DD + col) =
                make_float2(c[mt][nt][0] + b0, c[mt][nt][1] + b1);
            *(float2*)(C + (size_t)(row + 8) * DD + col) =
                make_float2(c[mt][nt][2] + b0, c[mt][nt][3] + b1);
        }
    }
}

// ---------------------------------------------------------------------------
// fp16 flash attention: Br=128, Bc=64, Q split / K,V single, P single-term.
// 3-stage KV pipeline, 1 sync/iter.
// ---------------------------------------------------------------------------
#define FRS 144
#define FOQ1 (128*FRS)
#define FOKV (2*128*FRS)          // 36864
#define FOV  (64*FRS)
#define FSTG (2*64*FRS)           // 18432 per stage
#define FATTN_SMEM (FOKV + 3*FSTG)   // 92160

__device__ __forceinline__ void load_kv_tile(
    uint32_t sb, uint32_t stgoff,
    const __half* Kg, const __half* Vg,
    size_t gbase, int tid)
{
    const uint32_t base = sb + FOKV + stgoff;
    #pragma unroll
    for (int it = 0; it < 4; it++) {
        const int i2 = ((it & 1) << 8) + tid;
        const int r  = i2 >> 3;
        const int cb = (i2 & 7) * 16;
        const __half* sp = (it >> 1) ? Vg : Kg;
        const uint32_t off = (it >> 1) ? FOV : 0;
        CP16(base + off + (uint32_t)r * FRS + cb,
             sp + gbase + (size_t)r * DD + cb / 2);
    }
    CP_COMMIT();
}

__global__ __launch_bounds__(256, 1) void fattn_kernel(
    const __half* __restrict__ Q0g, const __half* __restrict__ Q1g,
    const __half* __restrict__ Kg,  const __half* __restrict__ Vg,
    __half* __restrict__ A0out, __half* __restrict__ A1out)
{
    extern __shared__ char smem[];
    const uint32_t sb = smem_u32(smem);
    const int tid  = threadIdx.x;
    const int wid  = tid >> 5;
    const int lane = tid & 31;
    const int gid  = lane >> 2;
    const int t4   = lane & 3;

    const int qtile = (gridDim.x - 1) - blockIdx.x;
    const int q0 = qtile * 128;
    const int b  = blockIdx.y >> 4;
    const int h  = blockIdx.y & 15;
    const size_t hb = (size_t)(b * TT) * DD + h * HD;

    #pragma unroll
    for (int it = 0; it < 8; it++) {
        const int i2 = ((it & 3) << 8) + tid;
        const int r  = i2 >> 3;
        const int cb = (i2 & 7) * 16;
        const __half* sp = (it >> 2) ? Q1g : Q0g;
        const uint32_t off = (it >> 2) ? FOQ1 : 0;
        CP16(sb + off + (uint32_t)r * FRS + cb,
             sp + hb + (size_t)(q0 + r) * DD + cb / 2);
    }
    CP_COMMIT();

    const int ntiles = q0 / 64 + 2;
    load_kv_tile(sb, 0,    Kg, Vg, hb, tid);
    load_kv_tile(sb, FSTG, Kg, Vg, hb + (size_t)64 * DD, tid);

    const uint32_t qa0 = sb + (uint32_t)(wid * 16 + (lane & 15)) * FRS
                       + (uint32_t)(lane >> 4) * 16;
    const uint32_t qa1 = qa0 + FOQ1;
    const uint32_t kb4 = sb + FOKV + (uint32_t)(lane & 15) * FRS
                       + (uint32_t)(lane >> 4) * 16;
    const uint32_t vb4 = sb + FOKV + FOV + (uint32_t)(lane & 15) * FRS
                       + (uint32_t)(lane >> 4) * 16;

    float oc[8][4];
    #pragma unroll
    for (int nt = 0; nt < 8; nt++)
        #pragma unroll
        for (int e = 0; e < 4; e++) oc[nt][e] = 0.f;
    float m0v = -1e30f, m1v = -1e30f, l0 = 0.f, l1 = 0.f;

    const int r0 = q0 + wid * 16 + gid;
    const int r1 = r0 + 8;

    uint32_t cur = 0;
    for (int kt = 0; kt < ntiles; kt++) {
        const int kv0 = kt * 64;
        if (kt + 1 < ntiles) CP_WAIT1(); else CP_WAIT0();
        __syncthreads();

        if (kt + 2 < ntiles) {
            uint32_t pre = cur + 2 * FSTG;
            if (pre >= 3 * FSTG) pre -= 3 * FSTG;
            load_kv_tile(sb, pre, Kg, Vg, hb + (size_t)(kv0 + 128) * DD, tid);
        }

        // ---- S = (Q0+Q1) K^T ----
        float sc[8][4];
        #pragma unroll
        for (int nt = 0; nt < 8; nt++)
            #pragma unroll
            for (int e = 0; e < 4; e++) sc[nt][e] = 0.f;

        #pragma unroll
        for (int ks = 0; ks < 4; ks++) {
            uint32_t ah[4], al[4];
            LDSM_X4(ah, qa0 + ks * 32);
            LDSM_X4(al, qa1 + ks * 32);
            #pragma unroll
            for (int ntp = 0; ntp < 4; ntp++) {
                uint32_t bk[4];
                const uint32_t ka = kb4 + cur + (uint32_t)(ntp * 16) * FRS + ks * 32;
                LDSM_X4(bk, ka);
                MMA_F16(sc[2*ntp],   ah, bk[0], bk[2]);
                MMA_F16(sc[2*ntp],   al, bk[0], bk[2]);
                MMA_F16(sc[2*ntp+1], ah, bk[1], bk[3]);
                MMA_F16(sc[2*ntp+1], al, bk[1], bk[3]);
            }
        }

        const bool maskt = (kt >= ntiles - 2);
        #pragma unroll
        for (int nt = 0; nt < 8; nt++) {
            #pragma unroll
            for (int e = 0; e < 4; e++) {
                float s = sc[nt][e] * 0.125f;
                if (maskt) {
                    const int col = kv0 + nt * 8 + 2 * t4 + (e & 1);
                    const int row = (e < 2) ? r0 : r1;
                    if (col > row) s = -1e30f;
                }
                sc[nt][e] = s;
            }
        }

        float mx0 = -1e30f, mx1 = -1e30f;
        #pragma unroll
        for (int nt = 0; nt < 8; nt++) {
            mx0 = fmaxf(mx0, fmaxf(sc[nt][0], sc[nt][1]));
            mx1 = fmaxf(mx1, fmaxf(sc[nt][2], sc[nt][3]));
        }
        mx0 = fmaxf(mx0, __shfl_xor_sync(0xffffffffu, mx0, 1));
        mx0 = fmaxf(mx0, __shfl_xor_sync(0xffffffffu, mx0, 2));
        mx1 = fmaxf(mx1, __shfl_xor_sync(0xffffffffu, mx1, 1));
        mx1 = fmaxf(mx1, __shfl_xor_sync(0xffffffffu, mx1, 2));

        const float mn0 = fmaxf(m0v, mx0);
        const float mn1 = fmaxf(m1v, mx1);
        const float al0 = __expf(m0v - mn0);
        const float al1 = __expf(m1v - mn1);

        float s0 = 0.f, s1 = 0.f;
        #pragma unroll
        for (int nt = 0; nt < 8; nt++) {
            sc[nt][0] = __expf(sc[nt][0] - mn0);
            sc[nt][1] = __expf(sc[nt][1] - mn0);
            sc[nt][2] = __expf(sc[nt][2] - mn1);
            sc[nt][3] = __expf(sc[nt][3] - mn1);
            s0 += sc[nt][0] + sc[nt][1];
            s1 += sc[nt][2] + sc[nt][3];
        }
        s0 += __shfl_xor_sync(0xffffffffu, s0, 1);
        s0 += __shfl_xor_sync(0xffffffffu, s0, 2);
        s1 += __shfl_xor_sync(0xffffffffu, s1, 1);
        s1 += __shfl_xor_sync(0xffffffffu, s1, 2);
        l0 = l0 * al0 + s0;
        l1 = l1 * al1 + s1;
        #pragma unroll
        for (int nt = 0; nt < 8; nt++) {
            oc[nt][0] *= al0;
            oc[nt][1] *= al0;
            oc[nt][2] *= al1;
            oc[nt][3] *= al1;
        }
        m0v = mn0;
        m1v = mn1;

        // ---- O += P V (single term, P rounded to fp16) ----
        #pragma unroll
        for (int t = 0; t < 4; t++) {
            uint32_t ph[4];
            ph[0] = pack2h(sc[2*t][0],   sc[2*t][1]);
            ph[1] = pack2h(sc[2*t][2],   sc[2*t][3]);
            ph[2] = pack2h(sc[2*t+1][0], sc[2*t+1][1]);
            ph[3] = pack2h(sc[2*t+1][2], sc[2*t+1][3]);
            #pragma unroll
            for (int ntp = 0; ntp < 4; ntp++) {
                uint32_t vh[4];
                const uint32_t va = vb4 + cur + (uint32_t)(t * 16) * FRS + ntp * 32;
                LDSM_X4_T(vh, va);
                MMA_F16(oc[2*ntp],   ph, vh[0], vh[1]);
                MMA_F16(oc[2*ntp+1], ph, vh[2], vh[3]);
            }
        }

        cur += FSTG;
        if (cur == 3 * FSTG) cur = 0;
    }

    const float inv0 = 1.f / l0;
    const float inv1 = 1.f / l1;
    #pragma unroll
    for (int nt = 0; nt < 8; nt++) {
        const int col = nt * 8 + 2 * t4;
        uint32_t hh, ll;
        split2h(oc[nt][0] * inv0, oc[nt][1] * inv0, hh, ll);
        *(uint32_t*)(A0out + hb + (size_t)r0 * DD + col) = hh;
        *(uint32_t*)(A1out + hb + (size_t)r0 * DD + col) = ll;
        split2h(oc[nt][2] * inv1, oc[nt][3] * inv1, hh, ll);
        *(uint32_t*)(A0out + hb + (size_t)r1 * DD + col) = hh;
        *(uint32_t*)(A1out + hb + (size_t)r1 * DD + col) = ll;
    }
}

// ---------------------------------------------------------------------------
extern "C" void kernel_launch(void* const* d_in, const int* in_sizes, int n_in,
                              void* d_out, int out_size)
{
    (void)in_sizes; (void)n_in; (void)out_size;
    const float* x  = (const float*)d_in[0];
    const float* Wq = (const float*)d_in[2];
    const float* bq = (const float*)d_in[3];
    const float* Wk = (const float*)d_in[4];
    const float* bk = (const float*)d_in[5];
    const float* Wv = (const float*)d_in[6];
    const float* bv = (const float*)d_in[7];
    const float* Wo = (const float*)d_in[8];
    const float* bo = (const float*)d_in[9];
    float* out = (float*)d_out;

    __half *xh, *q0, *q1, *k, *v, *a0, *a1;
    cudaGetSymbolAddress((void**)&xh, g_x);
    cudaGetSymbolAddress((void**)&q0, g_q0);
    cudaGetSymbolAddress((void**)&q1, g_q1);
    cudaGetSymbolAddress((void**)&k,  g_k);
    cudaGetSymbolAddress((void**)&v,  g_v);
    cudaGetSymbolAddress((void**)&a0, g_a0);
    cudaGetSymbolAddress((void**)&a1, g_a1);
    __half *wq, *wk, *wv, *wo;
    cudaGetSymbolAddress((void**)&wq, g_wq);
    cudaGetSymbolAddress((void**)&wk, g_wk);
    cudaGetSymbolAddress((void**)&wv, g_wv);
    cudaGetSymbolAddress((void**)&wo, g_wo);

    cudaFuncSetAttribute(gemm_qkv_kernel,
                         cudaFuncAttributeMaxDynamicSharedMemorySize, QKV_SMEM);
    cudaFuncSetAttribute(gemm_o_kernel,
                         cudaFuncAttributeMaxDynamicSharedMemorySize, WO_SMEM);
    cudaFuncSetAttribute(fattn_kernel,
                         cudaFuncAttributeMaxDynamicSharedMemorySize, FATTN_SMEM);

    const int nElem = MROWS * DD;
    fhalf_kernel<<<nElem / 4 / 256, 256>>>(x, xh);

    TSplitArgs ts;
    ts.w[0] = Wq;  ts.w[1] = Wk;  ts.w[2] = Wv;  ts.w[3] = Wo;
    ts.th[0] = wq; ts.th[1] = wk; ts.th[2] = wv; ts.th[3] = wo;
    tsplit_kernel<<<dim3(DD / 32, DD / 32, 4), dim3(32, 8)>>>(ts);

    QKVArgs args;
    args.w[0] = wq; args.w[1] = wk; args.w[2] = wv;
    args.bias[0] = bq; args.bias[1] = bk; args.bias[2] = bv;
    args.ch[0] = q0; args.ch[1] = k; args.ch[2] = v;
    args.cl[0] = q1; args.cl[1] = nullptr; args.cl[2] = nullptr;

    gemm_qkv_kernel<<<dim3(24, MROWS / GM), 256, QKV_SMEM>>>(xh, args);

    fattn_kernel<<<dim3(TT / 128, BB * HH), 256, FATTN_SMEM>>>(
        q0, q1, k, v, a0, a1);

    gemm_o_kernel<<<dim3(DD / GN, MROWS / GM), 256, WO_SMEM>>>(
        a0, a1, wo, bo, out);
}

// round 16
// speedup vs baseline: 1.5873x; 1.1825x over previous
#include <cuda_runtime.h>
#include <cuda_fp16.h>
#include <math.h>
#include <stdint.h>

#define BB 2
#define TT 2048
#define DD 1024
#define HH 16
#define HD 64
#define MROWS (BB*TT)   // 4096

// ---------------------------------------------------------------------------
// Scratch (__device__ globals per allocation-free rule)
// ---------------------------------------------------------------------------
__device__ __half g_x[MROWS*DD];
__device__ __half g_q[MROWS*DD];
__device__ __half g_k[MROWS*DD];
__device__ __half g_v[MROWS*DD];
__device__ __half g_a[MROWS*DD];
__device__ __half g_wq[DD*DD], g_wk[DD*DD], g_wv[DD*DD], g_wo[DD*DD];

// ---------------------------------------------------------------------------
// PTX helpers
// ---------------------------------------------------------------------------
__device__ __forceinline__ uint32_t smem_u32(const void* p) {
    uint32_t a;
    asm("{ .reg .u64 t; cvta.to.shared.u64 t, %1; cvt.u32.u64 %0, t; }"
        : "=r"(a) : "l"(p));
    return a;
}

#define CP16(dst, src) \
    asm volatile("cp.async.cg.shared.global [%0], [%1], 16;" \
        :: "r"(dst), "l"(src) : "memory")
#define CP_COMMIT() asm volatile("cp.async.commit_group;" ::: "memory")
#define CP_WAIT1()  asm volatile("cp.async.wait_group 1;" ::: "memory")
#define CP_WAIT0()  asm volatile("cp.async.wait_group 0;" ::: "memory")

#define LDSM_X4(r, a) \
    asm volatile("ldmatrix.sync.aligned.m8n8.x4.shared.b16 {%0,%1,%2,%3}, [%4];" \
        : "=r"((r)[0]), "=r"((r)[1]), "=r"((r)[2]), "=r"((r)[3]) : "r"(a))
#define LDSM_X4_T(r, a) \
    asm volatile("ldmatrix.sync.aligned.m8n8.x4.trans.shared.b16 {%0,%1,%2,%3}, [%4];" \
        : "=r"((r)[0]), "=r"((r)[1]), "=r"((r)[2]), "=r"((r)[3]) : "r"(a))

#define MMA_F16(c, a, b0, b1) \
    asm volatile("mma.sync.aligned.m16n8k16.row.col.f32.f16.f16.f32 " \
        "{%0,%1,%2,%3}, {%4,%5,%6,%7}, {%8,%9}, {%0,%1,%2,%3};" \
        : "+f"((c)[0]), "+f"((c)[1]), "+f"((c)[2]), "+f"((c)[3]) \
        : "r"((a)[0]), "r"((a)[1]), "r"((a)[2]), "r"((a)[3]), \
          "r"(b0), "r"(b1))

__device__ __forceinline__ uint32_t pack2h(float x, float y) {
    __half2 h2(__float2half_rn(x), __float2half_rn(y));
    return *(uint32_t*)&h2;
}

// ---------------------------------------------------------------------------
// Prep kernels
// ---------------------------------------------------------------------------
__global__ void fhalf_kernel(const float* __restrict__ X,
                             __half* __restrict__ H)
{
    const int i = (blockIdx.x * blockDim.x + threadIdx.x) * 4;
    float4 xv = *(const float4*)(X + i);
    *(uint32_t*)(H + i)     = pack2h(xv.x, xv.y);
    *(uint32_t*)(H + i + 2) = pack2h(xv.z, xv.w);
}

struct TSplitArgs {
    const float* w[4];
    __half* th[4];
};

__global__ void tsplit_kernel(TSplitArgs args)
{
    __shared__ float t[32][33];
    const float* W = args.w[blockIdx.z];
    __half* Th = args.th[blockIdx.z];
    const int n0 = blockIdx.x * 32, k0 = blockIdx.y * 32;
    const int tx = threadIdx.x, ty = threadIdx.y;
    #pragma unroll
    for (int i = 0; i < 32; i += 8)
        t[ty + i][tx] = W[(size_t)(k0 + ty + i) * DD + n0 + tx];
    __syncthreads();
    #pragma unroll
    for (int i = 0; i < 32; i += 8) {
        Th[(size_t)(n0 + ty + i) * DD + k0 + tx] =
            __float2half_rn(t[tx][ty + i]);
    }
}

// ---------------------------------------------------------------------------
// fp16 HMMA GEMM core (single-term): C = A @ B^T
// 256 threads, GBK=32, 3-stage cp.async, 1 sync/iter.
// ---------------------------------------------------------------------------
#define GM 128
#define GN 128
#define GBK 32
#define NKT (DD / GBK)       // 32
#define SSTRB 80
#define OMAT (128 * SSTRB)   // 10240
#define OB  OMAT
#define SSZ (2*OMAT)         // 20480 per stage
#define GEMM_SMEM (3*SSZ)    // 61440

struct QKVArgs {
    const __half* w[3];
    const float* bias[3];
    __half* ch[3];
};

__device__ __forceinline__ void gemm_core(
    uint32_t sb, int tid,
    const __half* A, const __half* B,
    int m0, int n0, float c[4][4][4])
{
    const int wid  = tid >> 5;
    const int lane = tid & 31;
    const int wm   = wid >> 2;
    const int wn   = wid & 3;

    const int lrow = tid >> 1;
    const int lce  = (tid & 1) * 16;
    const uint32_t dstoff = lrow * SSTRB + lce * 2;
    const __half* gA = A + (size_t)(m0 + lrow) * DD + lce;
    const __half* gB = B + (size_t)(n0 + lrow) * DD + lce;

    const uint32_t a_base = sb + (uint32_t)(wm * 64 + (lane & 15)) * SSTRB
                          + (uint32_t)(lane >> 4) * 16;
    const uint32_t b_base = sb + OB + (uint32_t)(wn * 32 + (lane & 15)) * SSTRB
                          + (uint32_t)(lane >> 4) * 16;

    #pragma unroll
    for (int mt = 0; mt < 4; mt++)
        #pragma unroll
        for (int nt = 0; nt < 4; nt++)
            #pragma unroll
            for (int i = 0; i < 4; i++) c[mt][nt][i] = 0.f;

    auto stage_load = [&](uint32_t s, int ko) {
        CP16(s,       gA + ko);  CP16(s + 16,      gA + ko + 8);
        CP16(s + OB,  gB + ko);  CP16(s + OB + 16, gB + ko + 8);
        CP_COMMIT();
    };

    stage_load(sb + dstoff,       0);
    stage_load(sb + SSZ + dstoff, GBK);

    uint32_t cur = 0;
    for (int kt = 0; kt < NKT; kt++) {
        if (kt + 1 < NKT) CP_WAIT1(); else CP_WAIT0();
        __syncthreads();

        if (kt + 2 < NKT) {
            uint32_t pre = cur + 2 * SSZ;
            if (pre >= 3 * SSZ) pre -= 3 * SSZ;
            stage_load(sb + pre + dstoff, (kt + 2) * GBK);
        }

        #pragma unroll
        for (int ks = 0; ks < 2; ks++) {
            const uint32_t ksb = cur + ks * 32;
            uint32_t aa[4][4], bb[2][4];
            #pragma unroll
            for (int mt = 0; mt < 4; mt++)
                LDSM_X4(aa[mt], a_base + ksb + (uint32_t)(mt * 16) * SSTRB);
            #pragma unroll
            for (int ntp = 0; ntp < 2; ntp++)
                LDSM_X4(bb[ntp], b_base + ksb + (uint32_t)(ntp * 16) * SSTRB);
            #pragma unroll
            for (int mt = 0; mt < 4; mt++)
                #pragma unroll
                for (int ntp = 0; ntp < 2; ntp++) {
                    MMA_F16(c[mt][2*ntp],   aa[mt], bb[ntp][0], bb[ntp][2]);
                    MMA_F16(c[mt][2*ntp+1], aa[mt], bb[ntp][1], bb[ntp][3]);
                }
        }

        cur += SSZ;
        if (cur == 3 * SSZ) cur = 0;
    }
}

// Fused QKV GEMM: all outputs single fp16.
__global__ __launch_bounds__(256, 1) void gemm_qkv_kernel(
    const __half* __restrict__ A, QKVArgs args)
{
    extern __shared__ char smem[];
    const uint32_t sb = smem_u32(smem);
    const int tid  = threadIdx.x;
    const int widx = blockIdx.x >> 3;
    const int n0   = (blockIdx.x & 7) * GN;
    const int m0   = blockIdx.y * GM;

    float c[4][4][4];
    gemm_core(sb, tid, A, args.w[widx], m0, n0, c);

    const float* bias = args.bias[widx];
    __half* Ch = args.ch[widx];
    const int wid  = tid >> 5;
    const int lane = tid & 31;
    const int wm = wid >> 2, wn = wid & 3;
    const int lr = lane >> 2, lc = lane & 3;
    #pragma unroll
    for (int mt = 0; mt < 4; mt++) {
        const int row = m0 + wm * 64 + mt * 16 + lr;
        #pragma unroll
        for (int nt = 0; nt < 4; nt++) {
            const int col = n0 + wn * 32 + nt * 8 + 2 * lc;
            const float b0 = bias[col], b1 = bias[col + 1];
            *(uint32_t*)(Ch + (size_t)row * DD + col) =
                pack2h(c[mt][nt][0] + b0, c[mt][nt][1] + b1);
            *(uint32_t*)(Ch + (size_t)(row + 8) * DD + col) =
                pack2h(c[mt][nt][2] + b0, c[mt][nt][3] + b1);
        }
    }
}

// Wo GEMM: fp32 output
__global__ __launch_bounds__(256, 1) void gemm_o_kernel(
    const __half* __restrict__ A, const __half* __restrict__ B,
    const float* __restrict__ bias, float* __restrict__ C)
{
    extern __shared__ char smem[];
    const uint32_t sb = smem_u32(smem);
    const int tid = threadIdx.x;
    const int n0  = blockIdx.x * GN;
    const int m0  = blockIdx.y * GM;

    float c[4][4][4];
    gemm_core(sb, tid, A, B, m0, n0, c);

    const int wid  = tid >> 5;
    const int lane = tid & 31;
    const int wm = wid >> 2, wn = wid & 3;
    const int lr = lane >> 2, lc = lane & 3;
    #pragma unroll
    for (int mt = 0; mt < 4; mt++) {
        const int row = m0 + wm * 64 + mt * 16 + lr;
        #pragma unroll
        for (int nt = 0; nt < 4; nt++) {
            const int col = n0 + wn * 32 + nt * 8 + 2 * lc;
            const float b0 = bias[col], b1 = bias[col + 1];
            *(float2*)(C + (size_t)row * DD + col) =
                make_float2(c[mt][nt][0] + b0, c[mt][nt][1] + b1);
            *(float2*)(C + (size_t)(row + 8) * DD + col) =
                make_float2(c[mt][nt][2] + b0, c[mt][nt][3] + b1);
        }
    }
}

// ---------------------------------------------------------------------------
// fp16 flash attention: Br=128, Bc=64, all operands single fp16.
// 3-stage KV pipeline, 1 sync/iter.
// ---------------------------------------------------------------------------
#define FRS 144
#define FOKV (128*FRS)            // Q region: 18432
#define FOV  (64*FRS)
#define FSTG (2*64*FRS)           // 18432 per stage
#define FATTN_SMEM (FOKV + 3*FSTG)   // 73728

__device__ __forceinline__ void load_kv_tile(
    uint32_t sb, uint32_t stgoff,
    const __half* Kg, const __half* Vg,
    size_t gbase, int tid)
{
    const uint32_t base = sb + FOKV + stgoff;
    #pragma unroll
    for (int it = 0; it < 4; it++) {
        const int i2 = ((it & 1) << 8) + tid;
        const int r  = i2 >> 3;
        const int cb = (i2 & 7) * 16;
        const __half* sp = (it >> 1) ? Vg : Kg;
        const uint32_t off = (it >> 1) ? FOV : 0;
        CP16(base + off + (uint32_t)r * FRS + cb,
             sp + gbase + (size_t)r * DD + cb / 2);
    }
    CP_COMMIT();
}

__global__ __launch_bounds__(256, 1) void fattn_kernel(
    const __half* __restrict__ Qg,
    const __half* __restrict__ Kg,  const __half* __restrict__ Vg,
    __half* __restrict__ Aout)
{
    extern __shared__ char smem[];
    const uint32_t sb = smem_u32(smem);
    const int tid  = threadIdx.x;
    const int wid  = tid >> 5;
    const int lane = tid & 31;
    const int gid  = lane >> 2;
    const int t4   = lane & 3;

    const int qtile = (gridDim.x - 1) - blockIdx.x;
    const int q0 = qtile * 128;
    const int b  = blockIdx.y >> 4;
    const int h  = blockIdx.y & 15;
    const size_t hb = (size_t)(b * TT) * DD + h * HD;

    // ---- load Q tile (single) ----
    #pragma unroll
    for (int it = 0; it < 4; it++) {
        const int i2 = (it << 8) + tid;
        const int r  = i2 >> 3;
        const int cb = (i2 & 7) * 16;
        CP16(sb + (uint32_t)r * FRS + cb,
             Qg + hb + (size_t)(q0 + r) * DD + cb / 2);
    }
    CP_COMMIT();

    const int ntiles = q0 / 64 + 2;
    load_kv_tile(sb, 0,    Kg, Vg, hb, tid);
    load_kv_tile(sb, FSTG, Kg, Vg, hb + (size_t)64 * DD, tid);

    const uint32_t qa = sb + (uint32_t)(wid * 16 + (lane & 15)) * FRS
                      + (uint32_t)(lane >> 4) * 16;
    const uint32_t kb4 = sb + FOKV + (uint32_t)(lane & 15) * FRS
                       + (uint32_t)(lane >> 4) * 16;
    const uint32_t vb4 = sb + FOKV + FOV + (uint32_t)(lane & 15) * FRS
                       + (uint32_t)(lane >> 4) * 16;

    float oc[8][4];
    #pragma unroll
    for (int nt = 0; nt < 8; nt++)
        #pragma unroll
        for (int e = 0; e < 4; e++) oc[nt][e] = 0.f;
    float m0v = -1e30f, m1v = -1e30f, l0 = 0.f, l1 = 0.f;

    const int r0 = q0 + wid * 16 + gid;
    const int r1 = r0 + 8;

    uint32_t cur = 0;
    for (int kt = 0; kt < ntiles; kt++) {
        const int kv0 = kt * 64;
        if (kt + 1 < ntiles) CP_WAIT1(); else CP_WAIT0();
        __syncthreads();

        if (kt + 2 < ntiles) {
            uint32_t pre = cur + 2 * FSTG;
            if (pre >= 3 * FSTG) pre -= 3 * FSTG;
            load_kv_tile(sb, pre, Kg, Vg, hb + (size_t)(kv0 + 128) * DD, tid);
        }

        // ---- S = Q K^T (single term) ----
        float sc[8][4];
        #pragma unroll
        for (int nt = 0; nt < 8; nt++)
            #pragma unroll
            for (int e = 0; e < 4; e++) sc[nt][e] = 0.f;

        #pragma unroll
        for (int ks = 0; ks < 4; ks++) {
            uint32_t ah[4];
            LDSM_X4(ah, qa + ks * 32);
            #pragma unroll
            for (int ntp = 0; ntp < 4; ntp++) {
                uint32_t bk[4];
                const uint32_t ka = kb4 + cur + (uint32_t)(ntp * 16) * FRS + ks * 32;
                LDSM_X4(bk, ka);
                MMA_F16(sc[2*ntp],   ah, bk[0], bk[2]);
                MMA_F16(sc[2*ntp+1], ah, bk[1], bk[3]);
            }
        }

        const bool maskt = (kt >= ntiles - 2);
        #pragma unroll
        for (int nt = 0; nt < 8; nt++) {
            #pragma unroll
            for (int e = 0; e < 4; e++) {
                float s = sc[nt][e] * 0.125f;
                if (maskt) {
                    const int col = kv0 + nt * 8 + 2 * t4 + (e & 1);
                    const int row = (e < 2) ? r0 : r1;
                    if (col > row) s = -1e30f;
                }
                sc[nt][e] = s;
            }
        }

        float mx0 = -1e30f, mx1 = -1e30f;
        #pragma unroll
        for (int nt = 0; nt < 8; nt++) {
            mx0 = fmaxf(mx0, fmaxf(sc[nt][0], sc[nt][1]));
            mx1 = fmaxf(mx1, fmaxf(sc[nt][2], sc[nt][3]));
        }
        mx0 = fmaxf(mx0, __shfl_xor_sync(0xffffffffu, mx0, 1));
        mx0 = fmaxf(mx0, __shfl_xor_sync(0xffffffffu, mx0, 2));
        mx1 = fmaxf(mx1, __shfl_xor_sync(0xffffffffu, mx1, 1));
        mx1 = fmaxf(mx1, __shfl_xor_sync(0xffffffffu, mx1, 2));

        const float mn0 = fmaxf(m0v, mx0);
        const float mn1 = fmaxf(m1v, mx1);
        const float al0 = __expf(m0v - mn0);
        const float al1 = __expf(m1v - mn1);

        float s0 = 0.f, s1 = 0.f;
        #pragma unroll
        for (int nt = 0; nt < 8; nt++) {
            sc[nt][0] = __expf(sc[nt][0] - mn0);
            sc[nt][1] = __expf(sc[nt][1] - mn0);
            sc[nt][2] = __expf(sc[nt][2] - mn1);
            sc[nt][3] = __expf(sc[nt][3] - mn1);
            s0 += sc[nt][0] + sc[nt][1];
            s1 += sc[nt][2] + sc[nt][3];
        }
        s0 += __shfl_xor_sync(0xffffffffu, s0, 1);
        s0 += __shfl_xor_sync(0xffffffffu, s0, 2);
        s1 += __shfl_xor_sync(0xffffffffu, s1, 1);
        s1 += __shfl_xor_sync(0xffffffffu, s1, 2);
        l0 = l0 * al0 + s0;
        l1 = l1 * al1 + s1;
        #pragma unroll
        for (int nt = 0; nt < 8; nt++) {
            oc[nt][0] *= al0;
            oc[nt][1] *= al0;
            oc[nt][2] *= al1;
            oc[nt][3] *= al1;
        }
        m0v = mn0;
        m1v = mn1;

        // ---- O += P V (single term) ----
        #pragma unroll
        for (int t = 0; t < 4; t++) {
            uint32_t ph[4];
            ph[0] = pack2h(sc[2*t][0],   sc[2*t][1]);
            ph[1] = pack2h(sc[2*t][2],   sc[2*t][3]);
            ph[2] = pack2h(sc[2*t+1][0], sc[2*t+1][1]);
            ph[3] = pack2h(sc[2*t+1][2], sc[2*t+1][3]);
            #pragma unroll
            for (int ntp = 0; ntp < 4; ntp++) {
                uint32_t vh[4];
                const uint32_t va = vb4 + cur + (uint32_t)(t * 16) * FRS + ntp * 32;
                LDSM_X4_T(vh, va);
                MMA_F16(oc[2*ntp],   ph, vh[0], vh[1]);
                MMA_F16(oc[2*ntp+1], ph, vh[2], vh[3]);
            }
        }

        cur += FSTG;
        if (cur == 3 * FSTG) cur = 0;
    }

    const float inv0 = 1.f / l0;
    const float inv1 = 1.f / l1;
    #pragma unroll
    for (int nt = 0; nt < 8; nt++) {
        const int col = nt * 8 + 2 * t4;
        *(uint32_t*)(Aout + hb + (size_t)r0 * DD + col) =
            pack2h(oc[nt][0] * inv0, oc[nt][1] * inv0);
        *(uint32_t*)(Aout + hb + (size_t)r1 * DD + col) =
            pack2h(oc[nt][2] * inv1, oc[nt][3] * inv1);
    }
}

// ---------------------------------------------------------------------------
extern "C" void kernel_launch(void* const* d_in, const int* in_sizes, int n_in,
                              void* d_out, int out_size)
{
    (void)in_sizes; (void)n_in; (void)out_size;
    const float* x  = (const float*)d_in[0];
    const float* Wq = (const float*)d_in[2];
    const float* bq = (const float*)d_in[3];
    const float* Wk = (const float*)d_in[4];
    const float* bk = (const float*)d_in[5];
    const float* Wv = (const float*)d_in[6];
    const float* bv = (const float*)d_in[7];
    const float* Wo = (const float*)d_in[8];
    const float* bo = (const float*)d_in[9];
    float* out = (float*)d_out;

    __half *xh, *q, *k, *v, *a;
    cudaGetSymbolAddress((void**)&xh, g_x);
    cudaGetSymbolAddress((void**)&q,  g_q);
    cudaGetSymbolAddress((void**)&k,  g_k);
    cudaGetSymbolAddress((void**)&v,  g_v);
    cudaGetSymbolAddress((void**)&a,  g_a);
    __half *wq, *wk, *wv, *wo;
    cudaGetSymbolAddress((void**)&wq, g_wq);
    cudaGetSymbolAddress((void**)&wk, g_wk);
    cudaGetSymbolAddress((void**)&wv, g_wv);
    cudaGetSymbolAddress((void**)&wo, g_wo);

    cudaFuncSetAttribute(gemm_qkv_kernel,
                         cudaFuncAttributeMaxDynamicSharedMemorySize, GEMM_SMEM);
    cudaFuncSetAttribute(gemm_o_kernel,
                         cudaFuncAttributeMaxDynamicSharedMemorySize, GEMM_SMEM);
    cudaFuncSetAttribute(fattn_kernel,
                         cudaFuncAttributeMaxDynamicSharedMemorySize, FATTN_SMEM);

    const int nElem = MROWS * DD;
    fhalf_kernel<<<nElem / 4 / 256, 256>>>(x, xh);

    TSplitArgs ts;
    ts.w[0] = Wq;  ts.w[1] = Wk;  ts.w[2] = Wv;  ts.w[3] = Wo;
    ts.th[0] = wq; ts.th[1] = wk; ts.th[2] = wv; ts.th[3] = wo;
    tsplit_kernel<<<dim3(DD / 32, DD / 32, 4), dim3(32, 8)>>>(ts);

    QKVArgs args;
    args.w[0] = wq; args.w[1] = wk; args.w[2] = wv;
    args.bias[0] = bq; args.bias[1] = bk; args.bias[2] = bv;
    args.ch[0] = q; args.ch[1] = k; args.ch[2] = v;

    gemm_qkv_kernel<<<dim3(24, MROWS / GM), 256, GEMM_SMEM>>>(xh, args);

    fattn_kernel<<<dim3(TT / 128, BB * HH), 256, FATTN_SMEM>>>(
        q, k, v, a);

    gemm_o_kernel<<<dim3(DD / GN, MROWS / GM), 256, GEMM_SMEM>>>(
        a, wo, bo, out);
}

// round 17
// speedup vs baseline: 1.7057x; 1.0746x over previous
#include <cuda_runtime.h>
#include <cuda_fp16.h>
#include <math.h>
#include <stdint.h>

#define BB 2
#define TT 2048
#define DD 1024
#define HH 16
#define HD 64
#define MROWS (BB*TT)   // 4096

// ---------------------------------------------------------------------------
// Scratch (__device__ globals per allocation-free rule)
// ---------------------------------------------------------------------------
__device__ __half g_x[MROWS*DD];
__device__ __half g_q[MROWS*DD];
__device__ __half g_k[MROWS*DD];
__device__ __half g_v[MROWS*DD];
__device__ __half g_a[MROWS*DD];
__device__ __half g_wq[DD*DD], g_wk[DD*DD], g_wv[DD*DD], g_wo[DD*DD];

// ---------------------------------------------------------------------------
// PTX helpers
// ---------------------------------------------------------------------------
__device__ __forceinline__ uint32_t smem_u32(const void* p) {
    uint32_t a;
    asm("{ .reg .u64 t; cvta.to.shared.u64 t, %1; cvt.u32.u64 %0, t; }"
        : "=r"(a) : "l"(p));
    return a;
}

#define CP16(dst, src) \
    asm volatile("cp.async.cg.shared.global [%0], [%1], 16;" \
        :: "r"(dst), "l"(src) : "memory")
#define CP_COMMIT() asm volatile("cp.async.commit_group;" ::: "memory")
#define CP_WAIT1()  asm volatile("cp.async.wait_group 1;" ::: "memory")
#define CP_WAIT0()  asm volatile("cp.async.wait_group 0;" ::: "memory")

#define LDSM_X4(r, a) \
    asm volatile("ldmatrix.sync.aligned.m8n8.x4.shared.b16 {%0,%1,%2,%3}, [%4];" \
        : "=r"((r)[0]), "=r"((r)[1]), "=r"((r)[2]), "=r"((r)[3]) : "r"(a))
#define LDSM_X4_T(r, a) \
    asm volatile("ldmatrix.sync.aligned.m8n8.x4.trans.shared.b16 {%0,%1,%2,%3}, [%4];" \
        : "=r"((r)[0]), "=r"((r)[1]), "=r"((r)[2]), "=r"((r)[3]) : "r"(a))

#define MMA_F16(c, a, b0, b1) \
    asm volatile("mma.sync.aligned.m16n8k16.row.col.f32.f16.f16.f32 " \
        "{%0,%1,%2,%3}, {%4,%5,%6,%7}, {%8,%9}, {%0,%1,%2,%3};" \
        : "+f"((c)[0]), "+f"((c)[1]), "+f"((c)[2]), "+f"((c)[3]) \
        : "r"((a)[0]), "r"((a)[1]), "r"((a)[2]), "r"((a)[3]), \
          "r"(b0), "r"(b1))

__device__ __forceinline__ uint32_t pack2h(float x, float y) {
    __half2 h2(__float2half_rn(x), __float2half_rn(y));
    return *(uint32_t*)&h2;
}
__device__ __forceinline__ float ex2(float x) {
    float y;
    asm("ex2.approx.f32 %0, %1;" : "=f"(y) : "f"(x));
    return y;
}

// scale folded into Q: softmax(q.k/8) == exp2((q*SCL).k - m)
#define QSCL 0.18033688f   // 0.125 * log2(e)

// ---------------------------------------------------------------------------
// Prep kernels
// ---------------------------------------------------------------------------
__global__ void fhalf_kernel(const float* __restrict__ X,
                             __half* __restrict__ H)
{
    const int i = (blockIdx.x * blockDim.x + threadIdx.x) * 4;
    float4 xv = *(const float4*)(X + i);
    *(uint32_t*)(H + i)     = pack2h(xv.x, xv.y);
    *(uint32_t*)(H + i + 2) = pack2h(xv.z, xv.w);
}

struct TSplitArgs {
    const float* w[4];
    __half* th[4];
};

__global__ void tsplit_kernel(TSplitArgs args)
{
    __shared__ float t[32][33];
    const float* W = args.w[blockIdx.z];
    __half* Th = args.th[blockIdx.z];
    const int n0 = blockIdx.x * 32, k0 = blockIdx.y * 32;
    const int tx = threadIdx.x, ty = threadIdx.y;
    #pragma unroll
    for (int i = 0; i < 32; i += 8)
        t[ty + i][tx] = W[(size_t)(k0 + ty + i) * DD + n0 + tx];
    __syncthreads();
    #pragma unroll
    for (int i = 0; i < 32; i += 8) {
        Th[(size_t)(n0 + ty + i) * DD + k0 + tx] =
            __float2half_rn(t[tx][ty + i]);
    }
}

// ---------------------------------------------------------------------------
// fp16 HMMA GEMM core (single-term): C = A @ B^T
// ---------------------------------------------------------------------------
#define GM 128
#define GN 128
#define GBK 32
#define NKT (DD / GBK)
#define SSTRB 80
#define OMAT (128 * SSTRB)
#define OB  OMAT
#define SSZ (2*OMAT)
#define GEMM_SMEM (3*SSZ)    // 61440

struct QKVArgs {
    const __half* w[3];
    const float* bias[3];
    __half* ch[3];
};

__device__ __forceinline__ void gemm_core(
    uint32_t sb, int tid,
    const __half* A, const __half* B,
    int m0, int n0, float c[4][4][4])
{
    const int wid  = tid >> 5;
    const int lane = tid & 31;
    const int wm   = wid >> 2;
    const int wn   = wid & 3;

    const int lrow = tid >> 1;
    const int lce  = (tid & 1) * 16;
    const uint32_t dstoff = lrow * SSTRB + lce * 2;
    const __half* gA = A + (size_t)(m0 + lrow) * DD + lce;
    const __half* gB = B + (size_t)(n0 + lrow) * DD + lce;

    const uint32_t a_base = sb + (uint32_t)(wm * 64 + (lane & 15)) * SSTRB
                          + (uint32_t)(lane >> 4) * 16;
    const uint32_t b_base = sb + OB + (uint32_t)(wn * 32 + (lane & 15)) * SSTRB
                          + (uint32_t)(lane >> 4) * 16;

    #pragma unroll
    for (int mt = 0; mt < 4; mt++)
        #pragma unroll
        for (int nt = 0; nt < 4; nt++)
            #pragma unroll
            for (int i = 0; i < 4; i++) c[mt][nt][i] = 0.f;

    auto stage_load = [&](uint32_t s, int ko) {
        CP16(s,       gA + ko);  CP16(s + 16,      gA + ko + 8);
        CP16(s + OB,  gB + ko);  CP16(s + OB + 16, gB + ko + 8);
        CP_COMMIT();
    };

    stage_load(sb + dstoff,       0);
    stage_load(sb + SSZ + dstoff, GBK);

    uint32_t cur = 0;
    for (int kt = 0; kt < NKT; kt++) {
        if (kt + 1 < NKT) CP_WAIT1(); else CP_WAIT0();
        __syncthreads();

        if (kt + 2 < NKT) {
            uint32_t pre = cur + 2 * SSZ;
            if (pre >= 3 * SSZ) pre -= 3 * SSZ;
            stage_load(sb + pre + dstoff, (kt + 2) * GBK);
        }

        #pragma unroll
        for (int ks = 0; ks < 2; ks++) {
            const uint32_t ksb = cur + ks * 32;
            uint32_t aa[4][4], bb[2][4];
            #pragma unroll
            for (int mt = 0; mt < 4; mt++)
                LDSM_X4(aa[mt], a_base + ksb + (uint32_t)(mt * 16) * SSTRB);
            #pragma unroll
            for (int ntp = 0; ntp < 2; ntp++)
                LDSM_X4(bb[ntp], b_base + ksb + (uint32_t)(ntp * 16) * SSTRB);
            #pragma unroll
            for (int mt = 0; mt < 4; mt++)
                #pragma unroll
                for (int ntp = 0; ntp < 2; ntp++) {
                    MMA_F16(c[mt][2*ntp],   aa[mt], bb[ntp][0], bb[ntp][2]);
                    MMA_F16(c[mt][2*ntp+1], aa[mt], bb[ntp][1], bb[ntp][3]);
                }
        }

        cur += SSZ;
        if (cur == 3 * SSZ) cur = 0;
    }
}

// Fused QKV GEMM: Q (widx 0) additionally scaled by QSCL.
__global__ __launch_bounds__(256, 1) void gemm_qkv_kernel(
    const __half* __restrict__ A, QKVArgs args)
{
    extern __shared__ char smem[];
    const uint32_t sb = smem_u32(smem);
    const int tid  = threadIdx.x;
    const int widx = blockIdx.x >> 3;
    const int n0   = (blockIdx.x & 7) * GN;
    const int m0   = blockIdx.y * GM;

    float c[4][4][4];
    gemm_core(sb, tid, A, args.w[widx], m0, n0, c);

    const float* bias = args.bias[widx];
    __half* Ch = args.ch[widx];
    const float scl = (widx == 0) ? QSCL : 1.0f;
    const int wid  = tid >> 5;
    const int lane = tid & 31;
    const int wm = wid >> 2, wn = wid & 3;
    const int lr = lane >> 2, lc = lane & 3;
    #pragma unroll
    for (int mt = 0; mt < 4; mt++) {
        const int row = m0 + wm * 64 + mt * 16 + lr;
        #pragma unroll
        for (int nt = 0; nt < 4; nt++) {
            const int col = n0 + wn * 32 + nt * 8 + 2 * lc;
            const float b0 = bias[col], b1 = bias[col + 1];
            *(uint32_t*)(Ch + (size_t)row * DD + col) =
                pack2h((c[mt][nt][0] + b0) * scl, (c[mt][nt][1] + b1) * scl);
            *(uint32_t*)(Ch + (size_t)(row + 8) * DD + col) =
                pack2h((c[mt][nt][2] + b0) * scl, (c[mt][nt][3] + b1) * scl);
        }
    }
}

// Wo GEMM: fp32 output
__global__ __launch_bounds__(256, 1) void gemm_o_kernel(
    const __half* __restrict__ A, const __half* __restrict__ B,
    const float* __restrict__ bias, float* __restrict__ C)
{
    extern __shared__ char smem[];
    const uint32_t sb = smem_u32(smem);
    const int tid = threadIdx.x;
    const int n0  = blockIdx.x * GN;
    const int m0  = blockIdx.y * GM;

    float c[4][4][4];
    gemm_core(sb, tid, A, B, m0, n0, c);

    const int wid  = tid >> 5;
    const int lane = tid & 31;
    const int wm = wid >> 2, wn = wid & 3;
    const int lr = lane >> 2, lc = lane & 3;
    #pragma unroll
    for (int mt = 0; mt < 4; mt++) {
        const int row = m0 + wm * 64 + mt * 16 + lr;
        #pragma unroll
        for (int nt = 0; nt < 4; nt++) {
            const int col = n0 + wn * 32 + nt * 8 + 2 * lc;
            const float b0 = bias[col], b1 = bias[col + 1];
            *(float2*)(C + (size_t)row * DD + col) =
                make_float2(c[mt][nt][0] + b0, c[mt][nt][1] + b1);
            *(float2*)(C + (size_t)(row + 8) * DD + col) =
                make_float2(c[mt][nt][2] + b0, c[mt][nt][3] + b1);
        }
    }
}

// ---------------------------------------------------------------------------
// fp16 flash attention: Br=128, Bc=128, single-term, exp2-domain softmax.
// 3-stage KV pipeline, 1 sync/iter.
// ---------------------------------------------------------------------------
#define FRS 144
#define FBC 128
#define FOKV (128*FRS)            // Q region: 18432
#define FOV  (FBC*FRS)            // 18432
#define FSTG (2*FBC*FRS)          // 36864 per stage
#define FATTN_SMEM (FOKV + 3*FSTG)   // 129024

__device__ __forceinline__ void load_kv_tile(
    uint32_t sb, uint32_t stgoff,
    const __half* Kg, const __half* Vg,
    size_t gbase, int tid)
{
    const uint32_t base = sb + FOKV + stgoff;
    #pragma unroll
    for (int it = 0; it < 8; it++) {
        const int i2 = ((it & 3) << 8) + tid;        // 0..1023
        const int r  = i2 >> 3;                      // 0..127
        const int cb = (i2 & 7) * 16;
        const __half* sp = (it >> 2) ? Vg : Kg;
        const uint32_t off = (it >> 2) ? FOV : 0;
        CP16(base + off + (uint32_t)r * FRS + cb,
             sp + gbase + (size_t)r * DD + cb / 2);
    }
    CP_COMMIT();
}

__global__ __launch_bounds__(256, 1) void fattn_kernel(
    const __half* __restrict__ Qg,
    const __half* __restrict__ Kg,  const __half* __restrict__ Vg,
    __half* __restrict__ Aout)
{
    extern __shared__ char smem[];
    const uint32_t sb = smem_u32(smem);
    const int tid  = threadIdx.x;
    const int wid  = tid >> 5;
    const int lane = tid & 31;
    const int gid  = lane >> 2;
    const int t4   = lane & 3;

    const int qtile = (gridDim.x - 1) - blockIdx.x;
    const int q0 = qtile * 128;
    const int b  = blockIdx.y >> 4;
    const int h  = blockIdx.y & 15;
    const size_t hb = (size_t)(b * TT) * DD + h * HD;

    // ---- load Q tile ----
    #pragma unroll
    for (int it = 0; it < 4; it++) {
        const int i2 = (it << 8) + tid;
        const int r  = i2 >> 3;
        const int cb = (i2 & 7) * 16;
        CP16(sb + (uint32_t)r * FRS + cb,
             Qg + hb + (size_t)(q0 + r) * DD + cb / 2);
    }
    CP_COMMIT();

    const int ntiles = q0 / FBC + 1;
    load_kv_tile(sb, 0, Kg, Vg, hb, tid);
    if (ntiles > 1)
        load_kv_tile(sb, FSTG, Kg, Vg, hb + (size_t)FBC * DD, tid);

    const uint32_t qa = sb + (uint32_t)(wid * 16 + (lane & 15)) * FRS
                      + (uint32_t)(lane >> 4) * 16;
    const uint32_t kb4 = sb + FOKV + (uint32_t)(lane & 15) * FRS
                       + (uint32_t)(lane >> 4) * 16;
    const uint32_t vb4 = sb + FOKV + FOV + (uint32_t)(lane & 15) * FRS
                       + (uint32_t)(lane >> 4) * 16;

    float oc[8][4];
    #pragma unroll
    for (int nt = 0; nt < 8; nt++)
        #pragma unroll
        for (int e = 0; e < 4; e++) oc[nt][e] = 0.f;
    float m0v = -1e30f, m1v = -1e30f, l0 = 0.f, l1 = 0.f;

    const int r0 = q0 + wid * 16 + gid;
    const int r1 = r0 + 8;

    uint32_t cur = 0;
    for (int kt = 0; kt < ntiles; kt++) {
        const int kv0 = kt * FBC;
        if (kt + 1 < ntiles) CP_WAIT1(); else CP_WAIT0();
        __syncthreads();

        if (kt + 2 < ntiles) {
            uint32_t pre = cur + 2 * FSTG;
            if (pre >= 3 * FSTG) pre -= 3 * FSTG;
            load_kv_tile(sb, pre, Kg, Vg, hb + (size_t)(kv0 + 2 * FBC) * DD, tid);
        }

        // ---- S' = Q' K^T (exp2 domain; scale pre-folded into Q) ----
        float sc[16][4];
        #pragma unroll
        for (int nt = 0; nt < 16; nt++)
            #pragma unroll
            for (int e = 0; e < 4; e++) sc[nt][e] = 0.f;

        #pragma unroll
        for (int ks = 0; ks < 4; ks++) {
            uint32_t ah[4];
            LDSM_X4(ah, qa + ks * 32);
            #pragma unroll
            for (int ntp = 0; ntp < 8; ntp++) {
                uint32_t bk[4];
                const uint32_t ka = kb4 + cur + (uint32_t)(ntp * 16) * FRS + ks * 32;
                LDSM_X4(bk, ka);
                MMA_F16(sc[2*ntp],   ah, bk[0], bk[2]);
                MMA_F16(sc[2*ntp+1], ah, bk[1], bk[3]);
            }
        }

        // ---- causal mask (last tile only) ----
        if (kt == ntiles - 1) {
            #pragma unroll
            for (int nt = 0; nt < 16; nt++) {
                #pragma unroll
                for (int e = 0; e < 4; e++) {
                    const int col = kv0 + nt * 8 + 2 * t4 + (e & 1);
                    const int row = (e < 2) ? r0 : r1;
                    if (col > row) sc[nt][e] = -1e30f;
                }
            }
        }

        // ---- online softmax (exp2 domain) ----
        float mx0 = -1e30f, mx1 = -1e30f;
        #pragma unroll
        for (int nt = 0; nt < 16; nt++) {
            mx0 = fmaxf(mx0, fmaxf(sc[nt][0], sc[nt][1]));
            mx1 = fmaxf(mx1, fmaxf(sc[nt][2], sc[nt][3]));
        }
        mx0 = fmaxf(mx0, __shfl_xor_sync(0xffffffffu, mx0, 1));
        mx0 = fmaxf(mx0, __shfl_xor_sync(0xffffffffu, mx0, 2));
        mx1 = fmaxf(mx1, __shfl_xor_sync(0xffffffffu, mx1, 1));
        mx1 = fmaxf(mx1, __shfl_xor_sync(0xffffffffu, mx1, 2));

        const float mn0 = fmaxf(m0v, mx0);
        const float mn1 = fmaxf(m1v, mx1);
        const float al0 = ex2(m0v - mn0);
        const float al1 = ex2(m1v - mn1);

        float s0 = 0.f, s1 = 0.f;
        #pragma unroll
        for (int nt = 0; nt < 16; nt++) {
            sc[nt][0] = ex2(sc[nt][0] - mn0);
            sc[nt][1] = ex2(sc[nt][1] - mn0);
            sc[nt][2] = ex2(sc[nt][2] - mn1);
            sc[nt][3] = ex2(sc[nt][3] - mn1);
            s0 += sc[nt][0] + sc[nt][1];
            s1 += sc[nt][2] + sc[nt][3];
        }
        s0 += __shfl_xor_sync(0xffffffffu, s0, 1);
        s0 += __shfl_xor_sync(0xffffffffu, s0, 2);
        s1 += __shfl_xor_sync(0xffffffffu, s1, 1);
        s1 += __shfl_xor_sync(0xffffffffu, s1, 2);
        l0 = l0 * al0 + s0;
        l1 = l1 * al1 + s1;
        #pragma unroll
        for (int nt = 0; nt < 8; nt++) {
            oc[nt][0] *= al0;
            oc[nt][1] *= al0;
            oc[nt][2] *= al1;
            oc[nt][3] *= al1;
        }
        m0v = mn0;
        m1v = mn1;

        // ---- O += P V (single term) ----
        #pragma unroll
        for (int t = 0; t < 8; t++) {
            uint32_t ph[4];
            ph[0] = pack2h(sc[2*t][0],   sc[2*t][1]);
            ph[1] = pack2h(sc[2*t][2],   sc[2*t][3]);
            ph[2] = pack2h(sc[2*t+1][0], sc[2*t+1][1]);
            ph[3] = pack2h(sc[2*t+1][2], sc[2*t+1][3]);
            #pragma unroll
            for (int ntp = 0; ntp < 4; ntp++) {
                uint32_t vh[4];
                const uint32_t va = vb4 + cur + (uint32_t)(t * 16) * FRS + ntp * 32;
                LDSM_X4_T(vh, va);
                MMA_F16(oc[2*ntp],   ph, vh[0], vh[1]);
                MMA_F16(oc[2*ntp+1], ph, vh[2], vh[3]);
            }
        }

        cur += FSTG;
        if (cur == 3 * FSTG) cur = 0;
    }

    const float inv0 = 1.f / l0;
    const float inv1 = 1.f / l1;
    #pragma unroll
    for (int nt = 0; nt < 8; nt++) {
        const int col = nt * 8 + 2 * t4;
        *(uint32_t*)(Aout + hb + (size_t)r0 * DD + col) =
            pack2h(oc[nt][0] * inv0, oc[nt][1] * inv0);
        *(uint32_t*)(Aout + hb + (size_t)r1 * DD + col) =
            pack2h(oc[nt][2] * inv1, oc[nt][3] * inv1);
    }
}

// ---------------------------------------------------------------------------
extern "C" void kernel_launch(void* const* d_in, const int* in_sizes, int n_in,
                              void* d_out, int out_size)
{
    (void)in_sizes; (void)n_in; (void)out_size;
    const float* x  = (const float*)d_in[0];
    const float* Wq = (const float*)d_in[2];
    const float* bq = (const float*)d_in[3];
    const float* Wk = (const float*)d_in[4];
    const float* bk = (const float*)d_in[5];
    const float* Wv = (const float*)d_in[6];
    const float* bv = (const float*)d_in[7];
    const float* Wo = (const float*)d_in[8];
    const float* bo = (const float*)d_in[9];
    float* out = (float*)d_out;

    __half *xh, *q, *k, *v, *a;
    cudaGetSymbolAddress((void**)&xh, g_x);
    cudaGetSymbolAddress((void**)&q,  g_q);
    cudaGetSymbolAddress((void**)&k,  g_k);
    cudaGetSymbolAddress((void**)&v,  g_v);
    cudaGetSymbolAddress((void**)&a,  g_a);
    __half *wq, *wk, *wv, *wo;
    cudaGetSymbolAddress((void**)&wq, g_wq);
    cudaGetSymbolAddress((void**)&wk, g_wk);
    cudaGetSymbolAddress((void**)&wv, g_wv);
    cudaGetSymbolAddress((void**)&wo, g_wo);

    cudaFuncSetAttribute(gemm_qkv_kernel,
                         cudaFuncAttributeMaxDynamicSharedMemorySize, GEMM_SMEM);
    cudaFuncSetAttribute(gemm_o_kernel,
                         cudaFuncAttributeMaxDynamicSharedMemorySize, GEMM_SMEM);
    cudaFuncSetAttribute(fattn_kernel,
                         cudaFuncAttributeMaxDynamicSharedMemorySize, FATTN_SMEM);

    const int nElem = MROWS * DD;
    fhalf_kernel<<<nElem / 4 / 256, 256>>>(x, xh);

    TSplitArgs ts;
    ts.w[0] = Wq;  ts.w[1] = Wk;  ts.w[2] = Wv;  ts.w[3] = Wo;
    ts.th[0] = wq; ts.th[1] = wk; ts.th[2] = wv; ts.th[3] = wo;
    tsplit_kernel<<<dim3(DD / 32, DD / 32, 4), dim3(32, 8)>>>(ts);

    QKVArgs args;
    args.w[0] = wq; args.w[1] = wk; args.w[2] = wv;
    args.bias[0] = bq; args.bias[1] = bk; args.bias[2] = bv;
    args.ch[0] = q; args.ch[1] = k; args.ch[2] = v;

    gemm_qkv_kernel<<<dim3(24, MROWS / GM), 256, GEMM_SMEM>>>(xh, args);

    fattn_kernel<<<dim3(TT / 128, BB * HH), 256, FATTN_SMEM>>>(
        q, k, v, a);

    gemm_o_kernel<<<dim3(DD / GN, MROWS / GM), 256, GEMM_SMEM>>>(
        a, wo, bo, out);
}